// round 9
// baseline (speedup 1.0000x reference)
#include <cuda_runtime.h>
#include <cstdint>

// ---------------------------------------------------------------------------
// Problem constants
// ---------------------------------------------------------------------------
#define T_STEPS 100
#define B_SZ    32
#define NIN     512
#define N_NEU   2048
#define A_AR    2
#define NC      4096                    // A*N output columns, c = a*2048+n
#define KROWS   4608                    // NIN + NC input rows
#define KCHUNK  144                     // 4608 / 32 k-chunks
#define NKC     32                      // number of k-chunks
#define NBY     8                       // k-splits (4 chunks each)
#define NBG     4                       // batch groups of 8
#define CPD     5                       // cp.async window depth (x2 buffers)
#define XIS_SZ  (T_STEPS * B_SZ * NIN)  // 1,638,400
#define SS_SZ   (T_STEPS * B_SZ * N_NEU)// 6,553,600 per area
// alpha = float32(exp(-0.1))
#define ALPHA_F 0.9048374180359595731642491f

// ---------------------------------------------------------------------------
// Device-global scratch (static — no allocation anywhere)
// ---------------------------------------------------------------------------
__device__ float         g_W[KROWS * NC];              // fused weights [k][c]
__device__ float         g_V[B_SZ * NC];               // membrane V [b][c]
__device__ float         g_P[NBY * B_SZ * NC];         // partials [by][b][c]
__device__ unsigned char g_mff[T_STEPS * NBG * NIN];   // ff spike masks per t
__device__ unsigned char g_m8[NBG * KROWS];            // current-step masks [bg][k]

// ---------------------------------------------------------------------------
// Packed f32x2 helpers (sm_103a) — immune to fast-math contraction
// ---------------------------------------------------------------------------
__device__ __forceinline__ unsigned long long pack2(unsigned lo, unsigned hi) {
    unsigned long long d;
    asm("mov.b64 %0, {%1, %2};" : "=l"(d) : "r"(lo), "r"(hi));
    return d;
}
__device__ __forceinline__ unsigned long long ffma2(unsigned long long a,
                                                    unsigned long long b,
                                                    unsigned long long c) {
    unsigned long long d;
    asm("fma.rn.f32x2 %0, %1, %2, %3;" : "=l"(d) : "l"(a), "l"(b), "l"(c));
    return d;
}
__device__ __forceinline__ unsigned long long fadd2(unsigned long long a,
                                                    unsigned long long b) {
    unsigned long long d;
    asm("add.rn.f32x2 %0, %1, %2;" : "=l"(d) : "l"(a), "l"(b));
    return d;
}
__device__ __forceinline__ float lo32(unsigned long long v) {
    return __uint_as_float((unsigned)v);
}
__device__ __forceinline__ float hi32(unsigned long long v) {
    return __uint_as_float((unsigned)(v >> 32));
}
// cp.async (LDGSTS) helpers
__device__ __forceinline__ void cp16(unsigned dst, const void* src) {
    asm volatile("cp.async.cg.shared.global [%0], [%1], 16;" :: "r"(dst), "l"(src));
}
__device__ __forceinline__ void cp_commit() {
    asm volatile("cp.async.commit_group;");
}
template <int N> __device__ __forceinline__ void cp_wait() {
    asm volatile("cp.async.wait_group %0;" :: "n"(N));
}

// ---------------------------------------------------------------------------
// Kernel 1: Poisson input spikes for all T -> Xis output region [t][b][i].
// ---------------------------------------------------------------------------
__global__ void __launch_bounds__(256) prep_spikes(const float* __restrict__ rates,
                                                   const float* __restrict__ noise,
                                                   float* __restrict__ out) {
    int idx = blockIdx.x * blockDim.x + threadIdx.x;
    if (idx >= XIS_SZ) return;
    float rt = rates[idx];
    float nz = noise[idx];
    out[idx] = (nz < __fmul_rn(rt, 1e-3f)) ? 1.0f : 0.0f;
}

// ---------------------------------------------------------------------------
// Kernel 1b: pack ff spike masks: g_mff[t][bg][i] bit b = spike(batch bg*8+b).
// ---------------------------------------------------------------------------
__global__ void __launch_bounds__(256) prep_masks(const float* __restrict__ out) {
    int idx = blockIdx.x * blockDim.x + threadIdx.x;    // t*NBG*NIN
    if (idx >= T_STEPS * NBG * NIN) return;
    int t  = idx / (NBG * NIN);
    int r  = idx - t * (NBG * NIN);
    int bg = r >> 9;
    int i  = r & (NIN - 1);
    unsigned m = 0;
#pragma unroll
    for (int b = 0; b < 8; b++) {
        float f = out[t * (B_SZ * NIN) + (bg * 8 + b) * NIN + i];
        m |= (f != 0.0f ? 1u : 0u) << b;
    }
    g_mff[idx] = (unsigned char)m;
}

// ---------------------------------------------------------------------------
// Kernel 2: fuse Win [A,NIN,N] and Wrec [S,A,N,N] into g_W[k][c].
// ---------------------------------------------------------------------------
__global__ void pack_w(const float* __restrict__ Win,
                       const float* __restrict__ Wrec) {
    const int total4 = KROWS * NC / 4;
    for (int idx = blockIdx.x * blockDim.x + threadIdx.x; idx < total4;
         idx += gridDim.x * blockDim.x) {
        int e = idx << 2;
        int k = e >> 12;              // / 4096
        int c = e & (NC - 1);
        int a = c >> 11;
        int n = c & (N_NEU - 1);
        float4 v;
        if (k < NIN) {
            v = *(const float4*)&Win[(a * NIN + k) * N_NEU + n];
        } else {
            int kr = k - NIN;
            int s  = kr >> 11;
            int m  = kr & (N_NEU - 1);
            v = *(const float4*)&Wrec[(((s * A_AR + a) * N_NEU) + m) * (size_t)N_NEU + n];
        }
        *(float4*)&g_W[e] = v;
    }
}

// ---------------------------------------------------------------------------
// Kernel 3: init: V = 0; g_m8 = [mff(t=0) | zero rec masks].
// ---------------------------------------------------------------------------
__global__ void __launch_bounds__(256) init_state() {
    int idx = blockIdx.x * blockDim.x + threadIdx.x;
    if (idx < NBG * KROWS) {
        int bg = idx / KROWS;
        int k  = idx - bg * KROWS;
        g_m8[idx] = (k < NIN) ? g_mff[bg * NIN + k] : (unsigned char)0;
    }
    if (idx < B_SZ * NC) g_V[idx] = 0.0f;
}

// ---------------------------------------------------------------------------
// Kernel B (per step): mask compact + cp.async-pipelined sparse GEMM.
// Grid: (16 col-tiles, 4 bg, 8 by). Block: 8 warps = 4 ksub x 2 cw.
// Phase 1: warps 0..3 read 144 mask bytes for chunk by*4+w, ballot-compact
//   ascending-k active rows (W byte offsets) + expand exact {0,1} floats.
// Phase 2: double-buffered cp.async.cg windows of CPD gathered 16B W rows
//   (L2 -> smem, no register cost), consumed ascending-i from LDS. Values and
//   order identical to prior rounds -> bit-exact.
// Reduce: ksub ascending fold (slim sbuf: only ksub 1..3 stored), by ascending
//   fold in step_update. Epilogue: coalesced STG.128 to g_P[by][b][c].
// ---------------------------------------------------------------------------
struct SmemP1 {
    unsigned list[4][KCHUNK];       // W byte offsets (k * NC * 4), ascending
    float    spk[4][KCHUNK][8];     // expanded spike floats
    int      cnt[4];
};
union SmemU {
    SmemP1 p1;
    unsigned long long sbuf[6][32][17];   // reduce buffer for ksub 1..3
};
#define SMEM_STAGE_OFF  ((sizeof(SmemU) + 15) & ~15ull)
#define SMEM_TOTAL_GEMM (SMEM_STAGE_OFF + 2 * CPD * 256 * 16)

__device__ __forceinline__ void fma_row(unsigned long long acc[4][4],
                                        float4 wv, const float* __restrict__ sp) {
    float4 sA = *(const float4*)sp;
    float4 sB = *(const float4*)(sp + 4);
    unsigned long long s2[4];
    s2[0] = pack2(__float_as_uint(sA.x), __float_as_uint(sA.y));
    s2[1] = pack2(__float_as_uint(sA.z), __float_as_uint(sA.w));
    s2[2] = pack2(__float_as_uint(sB.x), __float_as_uint(sB.y));
    s2[3] = pack2(__float_as_uint(sB.z), __float_as_uint(sB.w));
    unsigned wb[4] = {__float_as_uint(wv.x), __float_as_uint(wv.y),
                      __float_as_uint(wv.z), __float_as_uint(wv.w)};
#pragma unroll
    for (int c = 0; c < 4; c++) {
        unsigned long long w2 = pack2(wb[c], wb[c]);
#pragma unroll
        for (int j = 0; j < 4; j++)
            acc[c][j] = ffma2(w2, s2[j], acc[c][j]);
    }
}

__global__ void __launch_bounds__(256, 3) step_gemm() {
    extern __shared__ char dynsmem[];
    SmemU& sm = *(SmemU*)dynsmem;
    float4* stage = (float4*)(dynsmem + SMEM_STAGE_OFF);
    const unsigned stage_u32 =
        (unsigned)__cvta_generic_to_shared(stage) + threadIdx.x * 16u;

    const int tid  = threadIdx.x;
    const int w    = tid >> 5;
    const int lane = tid & 31;
    const int cw   = w & 1;          // column half within block
    const int ksub = w >> 1;         // 0..3
    const int bg   = blockIdx.y;     // batch group (8 batches)
    const int by   = blockIdx.z;     // partial index
    const int c0   = blockIdx.x * 256 + cw * 128 + lane * 4;

    // ---- Phase 1: warps 0..3 compact chunk (by*4 + w) for this bg ----
    if (w < 4) {
        const int kc = by * 4 + w;
        const int k0 = kc * KCHUNK;
        const unsigned char* __restrict__ mb = &g_m8[bg * KROWS + k0];
        int total = 0;
#pragma unroll
        for (int it = 0; it < 5; it++) {
            int r = it * 32 + lane;
            unsigned msk = (r < KCHUNK) ? (unsigned)mb[r] : 0u;
            bool act = msk != 0u;
            unsigned bal = __ballot_sync(0xFFFFFFFFu, act);
            if (act) {
                int pos = total + __popc(bal & ((1u << lane) - 1u));
                sm.p1.list[w][pos] = (unsigned)(k0 + r) * (NC * 4);
#pragma unroll
                for (int b = 0; b < 8; b++)
                    sm.p1.spk[w][pos][b] = (msk >> b) & 1u ? 1.0f : 0.0f;
            }
            total += __popc(bal);
        }
        if (lane == 0) sm.p1.cnt[w] = total;
    }
    __syncthreads();

    // ---- Phase 2: double-buffered cp.async W stream, ascending-i consume ----
    const int n = sm.p1.cnt[ksub];
    const unsigned* __restrict__ lst = sm.p1.list[ksub];
    const float*    __restrict__ spk = &sm.p1.spk[ksub][0][0];
    const char* __restrict__ wbase = (const char*)g_W + (unsigned)c0 * 4u;

    unsigned long long acc[4][4];
#pragma unroll
    for (int c = 0; c < 4; c++)
#pragma unroll
        for (int j = 0; j < 4; j++) acc[c][j] = 0ull;

    const int nwd = (n + CPD - 1) / CPD;   // uniform per warp
    if (nwd > 0) {
        // issue window 0 into buffer 0
#pragma unroll
        for (int r = 0; r < CPD; r++)
            if (r < n) cp16(stage_u32 + (unsigned)(r * 256) * 16u,
                            wbase + lst[r]);
        cp_commit();

        for (int wd = 0; wd < nwd; wd++) {
            const int buf = wd & 1;
            if (wd + 1 < nwd) {
                const int i1 = (wd + 1) * CPD;
                const unsigned dst = stage_u32 + (unsigned)(((buf ^ 1) * CPD) * 256) * 16u;
#pragma unroll
                for (int r = 0; r < CPD; r++)
                    if (i1 + r < n) cp16(dst + (unsigned)(r * 256) * 16u,
                                         wbase + lst[i1 + r]);
                cp_commit();
                cp_wait<1>();   // current window's group complete
            } else {
                cp_wait<0>();
            }
            const int i0 = wd * CPD;
            const int lim = (n - i0 < CPD) ? (n - i0) : CPD;
            for (int r = 0; r < lim; r++) {
                float4 wv = stage[(buf * CPD + r) * 256 + tid];
                fma_row(acc, wv, &spk[(i0 + r) * 8]);
            }
        }
    }

    __syncthreads();   // phase-1 data consumed; safe to reuse union as sbuf

    if (ksub > 0) {
#pragma unroll
        for (int c = 0; c < 4; c++)
#pragma unroll
            for (int j = 0; j < 4; j++)
                sm.sbuf[(ksub - 1) * 2 + cw][lane][c * 4 + j] = acc[c][j];
    }
    __syncthreads();

    if (ksub == 0) {
#pragma unroll
        for (int ks = 0; ks < 3; ks++) {   // folds ksub 1,2,3 in ascending order
#pragma unroll
            for (int c = 0; c < 4; c++)
#pragma unroll
                for (int j = 0; j < 4; j++)
                    acc[c][j] = fadd2(acc[c][j], sm.sbuf[ks * 2 + cw][lane][c * 4 + j]);
        }
        // transposed, coalesced stores: g_P[by][b][c0..c0+3]
#pragma unroll
        for (int j = 0; j < 4; j++) {
            int b = bg * 8 + 2 * j;
            float4 lo4 = make_float4(lo32(acc[0][j]), lo32(acc[1][j]),
                                     lo32(acc[2][j]), lo32(acc[3][j]));
            float4 hi4 = make_float4(hi32(acc[0][j]), hi32(acc[1][j]),
                                     hi32(acc[2][j]), hi32(acc[3][j]));
            *(float4*)&g_P[(unsigned)((by * B_SZ + b)     * NC) + c0] = lo4;
            *(float4*)&g_P[(unsigned)((by * B_SZ + b + 1) * NC) + c0] = hi4;
        }
    }
}

// ---------------------------------------------------------------------------
// Kernel C (per step): thread = (bg, c) owns all 8 batches of its group.
// Ordered by-ascending reduce of 8 partials, LIF update, threshold, output
// writes, new recurrent mask byte, ff mask copy for t+1. All coalesced.
// ---------------------------------------------------------------------------
__global__ void __launch_bounds__(256) step_update(float* __restrict__ out, int t) {
    int idx = blockIdx.x * blockDim.x + threadIdx.x;   // 0 .. 16383
    if (idx >= NBG * NC) return;
    int bg = idx >> 12;
    int c  = idx & (NC - 1);
    int a  = c >> 11;
    int n  = c & (N_NEU - 1);

    unsigned oldm = g_m8[bg * KROWS + NIN + c];   // previous spikes (8 batches)
    unsigned newm = 0;

#pragma unroll
    for (int b8 = 0; b8 < 8; b8++) {
        int b = bg * 8 + b8;
        float I = g_P[(0 * B_SZ + b) * NC + c];
#pragma unroll
        for (int by = 1; by < NBY; by++)
            I = __fadd_rn(I, g_P[(by * B_SZ + b) * NC + c]);

        float xd   = (oldm >> b8) & 1u ? 1.0f : 0.0f;
        float Vold = g_V[b * NC + c];
        float Vnew = __fadd_rn(__fmul_rn(__fmul_rn(ALPHA_F, Vold),
                                         __fsub_rn(1.0f, xd)), I);
        unsigned s = Vnew >= 1.0f ? 1u : 0u;
        g_V[b * NC + c] = Vnew;
        newm |= s << b8;
        out[XIS_SZ + a * SS_SZ + t * (B_SZ * N_NEU) + b * N_NEU + n] =
            s ? 1.0f : 0.0f;
    }

    g_m8[bg * KROWS + NIN + c] = (unsigned char)newm;
    if (c < NIN && t + 1 < T_STEPS)
        g_m8[bg * KROWS + c] = g_mff[((t + 1) * NBG + bg) * NIN + c];
}

// ---------------------------------------------------------------------------
// Launch: prep (4 kernels) + 100 x (gemm, update). Graph-capturable.
// ---------------------------------------------------------------------------
extern "C" void kernel_launch(void* const* d_in, const int* in_sizes, int n_in,
                              void* d_out, int out_size) {
    const float* rates = (const float*)d_in[0];
    const float* noise = (const float*)d_in[1];
    const float* Win   = (const float*)d_in[2];
    const float* Wrec  = (const float*)d_in[3];
    float* out = (float*)d_out;

    cudaFuncSetAttribute(step_gemm, cudaFuncAttributeMaxDynamicSharedMemorySize,
                         (int)SMEM_TOTAL_GEMM);

    prep_spikes<<<(XIS_SZ + 255) / 256, 256>>>(rates, noise, out);
    prep_masks<<<(T_STEPS * NBG * NIN + 255) / 256, 256>>>(out);
    pack_w<<<1024, 256>>>(Win, Wrec);
    init_state<<<(B_SZ * NC + 255) / 256, 256>>>();

    for (int t = 0; t < T_STEPS; t++) {
        step_gemm<<<dim3(16, NBG, NBY), 256, SMEM_TOTAL_GEMM>>>();
        step_update<<<(NBG * NC + 255) / 256, 256>>>(out, t);
    }
}

// round 10
// speedup vs baseline: 1.1854x; 1.1854x over previous
#include <cuda_runtime.h>
#include <cstdint>

// ---------------------------------------------------------------------------
// Problem constants
// ---------------------------------------------------------------------------
#define T_STEPS 100
#define B_SZ    32
#define NIN     512
#define N_NEU   2048
#define A_AR    2
#define NC      4096                    // A*N output columns, c = a*2048+n
#define KROWS   4608                    // NIN + NC input rows
#define KCHUNK  144                     // 4608 / 32 k-chunks
#define NKC     32                      // number of k-chunks
#define NBY     8                       // k-splits (4 chunks each)
#define NBG     4                       // batch groups of 8
#define NCT     16                      // column tiles
#define XIS_SZ  (T_STEPS * B_SZ * NIN)  // 1,638,400
#define SS_SZ   (T_STEPS * B_SZ * N_NEU)// 6,553,600 per area
// alpha = float32(exp(-0.1))
#define ALPHA_F 0.9048374180359595731642491f

// ---------------------------------------------------------------------------
// Device-global scratch (static — no allocation anywhere)
// ---------------------------------------------------------------------------
__device__ float         g_W[KROWS * NC];              // fused weights [k][c]
__device__ float         g_V[B_SZ * NC];               // membrane V [b][c]
__device__ float         g_P[NBY * B_SZ * NC];         // partials [by][b][c]
__device__ unsigned char g_mff[T_STEPS * NBG * NIN];   // ff spike masks per t
__device__ unsigned char g_m8[NBG * KROWS];            // current-step masks [bg][k]
__device__ int           g_done[NCT * NBG];            // per-(ct,bg) completion

// ---------------------------------------------------------------------------
// Packed f32x2 helpers (sm_103a) — immune to fast-math contraction
// ---------------------------------------------------------------------------
__device__ __forceinline__ unsigned long long pack2(unsigned lo, unsigned hi) {
    unsigned long long d;
    asm("mov.b64 %0, {%1, %2};" : "=l"(d) : "r"(lo), "r"(hi));
    return d;
}
__device__ __forceinline__ unsigned long long ffma2(unsigned long long a,
                                                    unsigned long long b,
                                                    unsigned long long c) {
    unsigned long long d;
    asm("fma.rn.f32x2 %0, %1, %2, %3;" : "=l"(d) : "l"(a), "l"(b), "l"(c));
    return d;
}
__device__ __forceinline__ unsigned long long fadd2(unsigned long long a,
                                                    unsigned long long b) {
    unsigned long long d;
    asm("add.rn.f32x2 %0, %1, %2;" : "=l"(d) : "l"(a), "l"(b));
    return d;
}
__device__ __forceinline__ float lo32(unsigned long long v) {
    return __uint_as_float((unsigned)v);
}
__device__ __forceinline__ float hi32(unsigned long long v) {
    return __uint_as_float((unsigned)(v >> 32));
}

// ---------------------------------------------------------------------------
// Kernel 1: Poisson input spikes for all T -> Xis output region [t][b][i].
// ---------------------------------------------------------------------------
__global__ void __launch_bounds__(256) prep_spikes(const float* __restrict__ rates,
                                                   const float* __restrict__ noise,
                                                   float* __restrict__ out) {
    int idx = blockIdx.x * blockDim.x + threadIdx.x;
    if (idx >= XIS_SZ) return;
    float rt = rates[idx];
    float nz = noise[idx];
    out[idx] = (nz < __fmul_rn(rt, 1e-3f)) ? 1.0f : 0.0f;
}

// ---------------------------------------------------------------------------
// Kernel 1b: pack ff spike masks: g_mff[t][bg][i] bit b = spike(batch bg*8+b).
// ---------------------------------------------------------------------------
__global__ void __launch_bounds__(256) prep_masks(const float* __restrict__ out) {
    int idx = blockIdx.x * blockDim.x + threadIdx.x;    // t*NBG*NIN
    if (idx >= T_STEPS * NBG * NIN) return;
    int t  = idx / (NBG * NIN);
    int r  = idx - t * (NBG * NIN);
    int bg = r >> 9;
    int i  = r & (NIN - 1);
    unsigned m = 0;
#pragma unroll
    for (int b = 0; b < 8; b++) {
        float f = out[t * (B_SZ * NIN) + (bg * 8 + b) * NIN + i];
        m |= (f != 0.0f ? 1u : 0u) << b;
    }
    g_mff[idx] = (unsigned char)m;
}

// ---------------------------------------------------------------------------
// Kernel 2: fuse Win [A,NIN,N] and Wrec [S,A,N,N] into g_W[k][c].
// ---------------------------------------------------------------------------
__global__ void pack_w(const float* __restrict__ Win,
                       const float* __restrict__ Wrec) {
    const int total4 = KROWS * NC / 4;
    for (int idx = blockIdx.x * blockDim.x + threadIdx.x; idx < total4;
         idx += gridDim.x * blockDim.x) {
        int e = idx << 2;
        int k = e >> 12;              // / 4096
        int c = e & (NC - 1);
        int a = c >> 11;
        int n = c & (N_NEU - 1);
        float4 v;
        if (k < NIN) {
            v = *(const float4*)&Win[(a * NIN + k) * N_NEU + n];
        } else {
            int kr = k - NIN;
            int s  = kr >> 11;
            int m  = kr & (N_NEU - 1);
            v = *(const float4*)&Wrec[(((s * A_AR + a) * N_NEU) + m) * (size_t)N_NEU + n];
        }
        *(float4*)&g_W[e] = v;
    }
}

// ---------------------------------------------------------------------------
// Kernel 3: init: V = 0; g_m8 = [mff(t=0) | zero rec masks]; g_done = 0.
// ---------------------------------------------------------------------------
__global__ void __launch_bounds__(256) init_state() {
    int idx = blockIdx.x * blockDim.x + threadIdx.x;
    if (idx < NBG * KROWS) {
        int bg = idx / KROWS;
        int k  = idx - bg * KROWS;
        g_m8[idx] = (k < NIN) ? g_mff[bg * NIN + k] : (unsigned char)0;
    }
    if (idx < B_SZ * NC) g_V[idx] = 0.0f;
    if (idx < NCT * NBG) g_done[idx] = 0;
}

// ---------------------------------------------------------------------------
// Kernel B (per step): fused compact + sparse GEMM + (last block) LIF update.
// Grid: (16 col-tiles, 4 bg, 8 by). Block: 8 warps = 4 ksub x 2 cw.
// Phase 1: warps 0..3 read 144 mask bytes for chunk by*4+w, ballot-compact
//   ascending-k active rows + expand exact {0,1} floats.
// Phase 2: R8 register-prefetch FMA loop (ascending i) — best known.
// Reduce: ksub ascending fold; coalesced STG.128 of partials to g_P[by][b][c].
// Finish: threadfence + atomic per-(ct,bg) counter; the 8th arriver performs
//   the LIF update for its 256 columns x 8 batches (by-ascending fold —
//   identical arithmetic to the old step_update), writes output spikes, new
//   recurrent mask bytes, ff mask for t+1, and resets the counter.
// ---------------------------------------------------------------------------
struct SmemP1 {
    unsigned list[4][KCHUNK];       // W byte offsets (k * NC * 4), ascending
    float    spk[4][KCHUNK][8];     // expanded spike floats
    int      cnt[4];
};
union SmemU {
    SmemP1 p1;
    unsigned long long sbuf[8][32][17];   // reduce buffer (16 u64 + pad)
};

__device__ __forceinline__ void fma_row(unsigned long long acc[4][4],
                                        float4 wv, const float* __restrict__ sp) {
    float4 sA = *(const float4*)sp;
    float4 sB = *(const float4*)(sp + 4);
    unsigned long long s2[4];
    s2[0] = pack2(__float_as_uint(sA.x), __float_as_uint(sA.y));
    s2[1] = pack2(__float_as_uint(sA.z), __float_as_uint(sA.w));
    s2[2] = pack2(__float_as_uint(sB.x), __float_as_uint(sB.y));
    s2[3] = pack2(__float_as_uint(sB.z), __float_as_uint(sB.w));
    unsigned wb[4] = {__float_as_uint(wv.x), __float_as_uint(wv.y),
                      __float_as_uint(wv.z), __float_as_uint(wv.w)};
#pragma unroll
    for (int c = 0; c < 4; c++) {
        unsigned long long w2 = pack2(wb[c], wb[c]);
#pragma unroll
        for (int j = 0; j < 4; j++)
            acc[c][j] = ffma2(w2, s2[j], acc[c][j]);
    }
}

__global__ void __launch_bounds__(256, 3) step_fused(float* __restrict__ out, int t) {
    __shared__ SmemU sm;
    __shared__ int s_win;

    const int tid  = threadIdx.x;
    const int w    = tid >> 5;
    const int lane = tid & 31;
    const int cw   = w & 1;          // column half within block
    const int ksub = w >> 1;         // 0..3
    const int ct   = blockIdx.x;
    const int bg   = blockIdx.y;     // batch group (8 batches)
    const int by   = blockIdx.z;     // partial index
    const int c0   = ct * 256 + cw * 128 + lane * 4;

    // ---- Phase 1: warps 0..3 compact chunk (by*4 + w) for this bg ----
    if (w < 4) {
        const int kc = by * 4 + w;
        const int k0 = kc * KCHUNK;
        const unsigned char* __restrict__ mb = &g_m8[bg * KROWS + k0];
        int total = 0;
#pragma unroll
        for (int it = 0; it < 5; it++) {
            int r = it * 32 + lane;
            unsigned msk = (r < KCHUNK) ? (unsigned)mb[r] : 0u;
            bool act = msk != 0u;
            unsigned bal = __ballot_sync(0xFFFFFFFFu, act);
            if (act) {
                int pos = total + __popc(bal & ((1u << lane) - 1u));
                sm.p1.list[w][pos] = (unsigned)(k0 + r) * (NC * 4);
#pragma unroll
                for (int b = 0; b < 8; b++)
                    sm.p1.spk[w][pos][b] = (msk >> b) & 1u ? 1.0f : 0.0f;
            }
            total += __popc(bal);
        }
        if (lane == 0) sm.p1.cnt[w] = total;
    }
    __syncthreads();

    // ---- Phase 2: sparse FMA loop, 4-row batched W prefetch (R8) ----
    const int n = sm.p1.cnt[ksub];
    const unsigned* __restrict__ lst = sm.p1.list[ksub];
    const float*    __restrict__ spk = &sm.p1.spk[ksub][0][0];
    const char* __restrict__ wbase = (const char*)g_W + (unsigned)c0 * 4u;

    unsigned long long acc[4][4];
#pragma unroll
    for (int c = 0; c < 4; c++)
#pragma unroll
        for (int j = 0; j < 4; j++) acc[c][j] = 0ull;

    int i = 0;
    for (; i + 4 <= n; i += 4) {
        uint4 off = *(const uint4*)&lst[i];           // one LDS.128: 4 offsets
        float4 wv0 = *(const float4*)(wbase + off.x); // 4 independent LDG.128
        float4 wv1 = *(const float4*)(wbase + off.y);
        float4 wv2 = *(const float4*)(wbase + off.z);
        float4 wv3 = *(const float4*)(wbase + off.w);
        fma_row(acc, wv0, &spk[(i + 0) * 8]);
        fma_row(acc, wv1, &spk[(i + 1) * 8]);
        fma_row(acc, wv2, &spk[(i + 2) * 8]);
        fma_row(acc, wv3, &spk[(i + 3) * 8]);
    }
    for (; i < n; i++) {
        unsigned off = lst[i];
        float4 wv = *(const float4*)(wbase + off);
        fma_row(acc, wv, &spk[i * 8]);
    }

    __syncthreads();   // phase-1 data consumed; safe to reuse shared

#pragma unroll
    for (int c = 0; c < 4; c++)
#pragma unroll
        for (int j = 0; j < 4; j++) sm.sbuf[w][lane][c * 4 + j] = acc[c][j];
    __syncthreads();

    if (ksub == 0) {
#pragma unroll
        for (int ks = 1; ks < 4; ks++) {
#pragma unroll
            for (int c = 0; c < 4; c++)
#pragma unroll
                for (int j = 0; j < 4; j++)
                    acc[c][j] = fadd2(acc[c][j], sm.sbuf[ks * 2 + cw][lane][c * 4 + j]);
        }
        // transposed, coalesced stores: g_P[by][b][c0..c0+3]
#pragma unroll
        for (int j = 0; j < 4; j++) {
            int b = bg * 8 + 2 * j;
            float4 lo4 = make_float4(lo32(acc[0][j]), lo32(acc[1][j]),
                                     lo32(acc[2][j]), lo32(acc[3][j]));
            float4 hi4 = make_float4(hi32(acc[0][j]), hi32(acc[1][j]),
                                     hi32(acc[2][j]), hi32(acc[3][j]));
            *(float4*)&g_P[(unsigned)((by * B_SZ + b)     * NC) + c0] = lo4;
            *(float4*)&g_P[(unsigned)((by * B_SZ + b + 1) * NC) + c0] = hi4;
        }
    }

    // ---- Completion signal: last of the 8 by-blocks updates (ct, bg) ----
    __threadfence();            // make this block's g_P stores globally visible
    __syncthreads();
    if (tid == 0) {
        int old = atomicAdd(&g_done[ct * NBG + bg], 1);
        s_win = (old == NBY - 1) ? 1 : 0;
    }
    __syncthreads();
    if (!s_win) return;

    __threadfence();            // acquire: all 8 blocks' g_P stores visible
    if (tid == 0) g_done[ct * NBG + bg] = 0;   // reset for next step

    // LIF update for c = ct*256 + tid, batches bg*8 .. bg*8+7
    {
        const int c = ct * 256 + tid;
        const int a = c >> 11;
        const int nn = c & (N_NEU - 1);

        unsigned oldm = g_m8[bg * KROWS + NIN + c];
        unsigned newm = 0;

#pragma unroll
        for (int b8 = 0; b8 < 8; b8++) {
            int b = bg * 8 + b8;
            float I = g_P[(0 * B_SZ + b) * NC + c];
#pragma unroll
            for (int byi = 1; byi < NBY; byi++)
                I = __fadd_rn(I, g_P[(byi * B_SZ + b) * NC + c]);

            float xd   = (oldm >> b8) & 1u ? 1.0f : 0.0f;
            float Vold = g_V[b * NC + c];
            float Vnew = __fadd_rn(__fmul_rn(__fmul_rn(ALPHA_F, Vold),
                                             __fsub_rn(1.0f, xd)), I);
            unsigned s = Vnew >= 1.0f ? 1u : 0u;
            g_V[b * NC + c] = Vnew;
            newm |= s << b8;
            out[XIS_SZ + a * SS_SZ + t * (B_SZ * N_NEU) + b * N_NEU + nn] =
                s ? 1.0f : 0.0f;
        }

        g_m8[bg * KROWS + NIN + c] = (unsigned char)newm;
        if (c < NIN && t + 1 < T_STEPS)
            g_m8[bg * KROWS + c] = g_mff[((t + 1) * NBG + bg) * NIN + c];
    }
}

// ---------------------------------------------------------------------------
// Launch: prep (4 kernels) + 100 x fused step. Graph-capturable.
// ---------------------------------------------------------------------------
extern "C" void kernel_launch(void* const* d_in, const int* in_sizes, int n_in,
                              void* d_out, int out_size) {
    const float* rates = (const float*)d_in[0];
    const float* noise = (const float*)d_in[1];
    const float* Win   = (const float*)d_in[2];
    const float* Wrec  = (const float*)d_in[3];
    float* out = (float*)d_out;

    prep_spikes<<<(XIS_SZ + 255) / 256, 256>>>(rates, noise, out);
    prep_masks<<<(T_STEPS * NBG * NIN + 255) / 256, 256>>>(out);
    pack_w<<<1024, 256>>>(Win, Wrec);
    init_state<<<(B_SZ * NC + 255) / 256, 256>>>();

    for (int t = 0; t < T_STEPS; t++) {
        step_fused<<<dim3(NCT, NBG, NBY), 256>>>(out, t);
    }
}